// round 1
// baseline (speedup 1.0000x reference)
#include <cuda_runtime.h>

// ---------------------------------------------------------------------------
// Shifted-window MSA (Swin SW block), fp32 baseline.
//   B=8, NSEQ=16384, C=256, P=64, SHIFT=32, NH=8, HD=32
//   pad = 0, so:
//     x_rolled[t] = x[(t+32) & 16383]
//     mask only on last window per batch: blocked iff (i^j)&32
//     final[t+32 mod n] = proj_out[t]
// Pipeline:
//   K1: QKV GEMM  (roll on A read)         -> g_qkv [131072 x 768]
//   K2: attention per (window, head)       -> g_att [131072 x 256]
//   K3: out GEMM  (roll on C write)        -> d_out
// ---------------------------------------------------------------------------

#define BATCH   8
#define NSEQ    16384
#define CDIM    256
#define PWIN    64
#define SHIFT   32
#define NHEADS  8
#define HDIM    32
#define MTOT    (BATCH * NSEQ)     // 131072
#define QKV_N   768
#define NWIN    (MTOT / PWIN)      // 2048 total windows
#define WPB     (NSEQ / PWIN)      // 256 windows per batch

// Scratch (static device arrays: allocation-free, graph-capturable)
__device__ float g_qkv[(size_t)MTOT * QKV_N];   // ~402 MB
__device__ float g_att[(size_t)MTOT * CDIM];    // ~134 MB

// ---------------------------------------------------------------------------
// Tiled fp32 GEMM:  C[m, n] = sum_c A'[m, c] * W[n, c] + bias[n]
//   A' row m:  if ROLL_A, reads x[bi, (t+32)&16383, :]  (m = bi*16384 + t)
//   C  row m:  if ROLL_OUT, writes out[bi, (t+32)&16383, :]
// BM=BN=128, BK=16, 256 threads, 8x8 register tile per thread.
// ---------------------------------------------------------------------------
template<bool ROLL_A, bool ROLL_OUT>
__global__ void gemm128_kernel(const float* __restrict__ A,
                               const float* __restrict__ W,
                               const float* __restrict__ bias,
                               float* __restrict__ Cout,
                               int Ncols)
{
    __shared__ float As[16][132];   // [k][m], padded stride (132*4 % 16 == 0)
    __shared__ float Bs[16][132];   // [k][n]

    const int bm = blockIdx.y * 128;
    const int bn = blockIdx.x * 128;

    const int tid  = threadIdx.x;
    const int tx   = tid & 15;   // n direction
    const int ty   = tid >> 4;   // m direction

    // ---- load-thread coordinates ----
    const int lrow = tid >> 2;          // 0..63
    const int lc4  = (tid & 3) * 4;     // 0,4,8,12 (k offset within BK)

    // A row pointers (2 rows per thread), with optional roll remap
    const float* aptr0;
    const float* aptr1;
    {
        int m0 = bm + lrow;
        int m1 = bm + lrow + 64;
        int bi0 = m0 >> 14, t0 = m0 & 16383;
        int bi1 = m1 >> 14, t1 = m1 & 16383;
        int s0 = ROLL_A ? ((t0 + SHIFT) & 16383) : t0;
        int s1 = ROLL_A ? ((t1 + SHIFT) & 16383) : t1;
        aptr0 = A + ((size_t)((bi0 << 14) + s0)) * CDIM;
        aptr1 = A + ((size_t)((bi1 << 14) + s1)) * CDIM;
    }
    const float* bptr0 = W + (size_t)(bn + lrow) * CDIM + lc4;
    const float* bptr1 = bptr0 + (size_t)64 * CDIM;

    float acc[8][8];
#pragma unroll
    for (int i = 0; i < 8; i++)
#pragma unroll
        for (int j = 0; j < 8; j++) acc[i][j] = 0.0f;

#pragma unroll 1
    for (int kt = 0; kt < 16; kt++) {
        const int k0 = kt * 16;

        float4 a0 = *(const float4*)(aptr0 + k0 + lc4);
        float4 a1 = *(const float4*)(aptr1 + k0 + lc4);
        float4 b0 = *(const float4*)(bptr0 + k0);
        float4 b1 = *(const float4*)(bptr1 + k0);

        __syncthreads();   // previous iteration's reads done

        As[lc4 + 0][lrow] = a0.x; As[lc4 + 1][lrow] = a0.y;
        As[lc4 + 2][lrow] = a0.z; As[lc4 + 3][lrow] = a0.w;
        As[lc4 + 0][lrow + 64] = a1.x; As[lc4 + 1][lrow + 64] = a1.y;
        As[lc4 + 2][lrow + 64] = a1.z; As[lc4 + 3][lrow + 64] = a1.w;

        Bs[lc4 + 0][lrow] = b0.x; Bs[lc4 + 1][lrow] = b0.y;
        Bs[lc4 + 2][lrow] = b0.z; Bs[lc4 + 3][lrow] = b0.w;
        Bs[lc4 + 0][lrow + 64] = b1.x; Bs[lc4 + 1][lrow + 64] = b1.y;
        Bs[lc4 + 2][lrow + 64] = b1.z; Bs[lc4 + 3][lrow + 64] = b1.w;

        __syncthreads();

#pragma unroll
        for (int k = 0; k < 16; k++) {
            float4 af0 = *(const float4*)&As[k][ty * 8];
            float4 af1 = *(const float4*)&As[k][ty * 8 + 4];
            float4 bf0 = *(const float4*)&Bs[k][tx * 8];
            float4 bf1 = *(const float4*)&Bs[k][tx * 8 + 4];
            float av[8] = {af0.x, af0.y, af0.z, af0.w, af1.x, af1.y, af1.z, af1.w};
            float bv[8] = {bf0.x, bf0.y, bf0.z, bf0.w, bf1.x, bf1.y, bf1.z, bf1.w};
#pragma unroll
            for (int i = 0; i < 8; i++)
#pragma unroll
                for (int j = 0; j < 8; j++)
                    acc[i][j] += av[i] * bv[j];
        }
    }

    // ---- epilogue: add bias, write (with optional output roll) ----
    float bfrag[8];
#pragma unroll
    for (int j = 0; j < 8; j++) bfrag[j] = bias[bn + tx * 8 + j];

#pragma unroll
    for (int i = 0; i < 8; i++) {
        int m = bm + ty * 8 + i;
        int bi = m >> 14, t = m & 16383;
        int dst = ROLL_OUT ? ((t + SHIFT) & 16383) : t;
        float* crow = Cout + ((size_t)((bi << 14) + dst)) * Ncols + bn + tx * 8;
        float4 o0, o1;
        o0.x = acc[i][0] + bfrag[0]; o0.y = acc[i][1] + bfrag[1];
        o0.z = acc[i][2] + bfrag[2]; o0.w = acc[i][3] + bfrag[3];
        o1.x = acc[i][4] + bfrag[4]; o1.y = acc[i][5] + bfrag[5];
        o1.z = acc[i][6] + bfrag[6]; o1.w = acc[i][7] + bfrag[7];
        *(float4*)(crow)     = o0;
        *(float4*)(crow + 4) = o1;
    }
}

// ---------------------------------------------------------------------------
// Attention per (window, head). 64 threads = one query row each.
//   sim[i][j] = scale * q_i . k_j + rel[i-j+63]; mask on last window/batch.
//   out[i][d] = (sum_j exp(sim) * v[j][d]) / (sum_j exp(sim))
// No probs materialization: accumulate e*v inline (all-register).
// ---------------------------------------------------------------------------
__global__ void attn_kernel(const float* __restrict__ qkv,
                            const float* __restrict__ rel_pos,
                            float* __restrict__ att)
{
    __shared__ float ks[64][36];
    __shared__ float vs[64][36];
    __shared__ float rel[128];

    const int wi = blockIdx.x;   // 0..2047
    const int h  = blockIdx.y;   // 0..7
    const int i  = threadIdx.x;  // 0..63 (query row)
    const int mbase = wi * PWIN;

    const float* rowp = qkv + (size_t)(mbase + i) * QKV_N + h * HDIM;

    float q[32];
#pragma unroll
    for (int d4 = 0; d4 < 8; d4++) {
        float4 vq = *(const float4*)(rowp + d4 * 4);
        float4 vk = *(const float4*)(rowp + 256 + d4 * 4);
        float4 vv = *(const float4*)(rowp + 512 + d4 * 4);
        q[d4 * 4 + 0] = vq.x; q[d4 * 4 + 1] = vq.y;
        q[d4 * 4 + 2] = vq.z; q[d4 * 4 + 3] = vq.w;
        *(float4*)&ks[i][d4 * 4] = vk;
        *(float4*)&vs[i][d4 * 4] = vv;
    }
    rel[i] = rel_pos[h * 127 + i];
    if (i < 63) rel[i + 64] = rel_pos[h * 127 + 64 + i];
    __syncthreads();

    const float scale = 0.17677669529663687f;  // 1/sqrt(32)
    const bool lastw = ((wi & (WPB - 1)) == (WPB - 1));

    float acc[32];
#pragma unroll
    for (int d = 0; d < 32; d++) acc[d] = 0.0f;
    float ssum = 0.0f;

#pragma unroll 4
    for (int j = 0; j < 64; j++) {
        float s = 0.0f;
#pragma unroll
        for (int d = 0; d < 32; d++) s += q[d] * ks[j][d];
        s = s * scale + rel[i - j + 63];
        if (lastw && ((i ^ j) & 32)) s = -1e30f;
        float e = __expf(s);
        ssum += e;
#pragma unroll
        for (int d = 0; d < 32; d++) acc[d] += e * vs[j][d];
    }

    const float inv = 1.0f / ssum;
    float* orow = att + (size_t)(mbase + i) * CDIM + h * HDIM;
#pragma unroll
    for (int d4 = 0; d4 < 8; d4++) {
        float4 o;
        o.x = acc[d4 * 4 + 0] * inv; o.y = acc[d4 * 4 + 1] * inv;
        o.z = acc[d4 * 4 + 2] * inv; o.w = acc[d4 * 4 + 3] * inv;
        *(float4*)(orow + d4 * 4) = o;
    }
}

// ---------------------------------------------------------------------------
extern "C" void kernel_launch(void* const* d_in, const int* in_sizes, int n_in,
                              void* d_out, int out_size)
{
    const float* x       = (const float*)d_in[0];
    const float* w_qkv   = (const float*)d_in[1];
    const float* b_qkv   = (const float*)d_in[2];
    const float* rel_pos = (const float*)d_in[3];
    const float* w_out   = (const float*)d_in[4];
    const float* b_out   = (const float*)d_in[5];
    float* out = (float*)d_out;

    float* qkvp = nullptr;
    float* attp = nullptr;
    cudaGetSymbolAddress((void**)&qkvp, g_qkv);
    cudaGetSymbolAddress((void**)&attp, g_att);

    // K1: QKV projection with input roll.  grid (768/128, 131072/128)
    {
        dim3 grid(QKV_N / 128, MTOT / 128);
        gemm128_kernel<true, false><<<grid, 256>>>(x, w_qkv, b_qkv, qkvp, QKV_N);
    }
    // K2: windowed attention. grid (2048 windows, 8 heads), 64 threads.
    {
        dim3 grid(NWIN, NHEADS);
        attn_kernel<<<grid, 64>>>(qkvp, rel_pos, attp);
    }
    // K3: output projection with output roll. grid (256/128, 131072/128)
    {
        dim3 grid(CDIM / 128, MTOT / 128);
        gemm128_kernel<false, true><<<grid, 256>>>(attp, w_out, b_out, out, CDIM);
    }
}

// round 2
// speedup vs baseline: 2.1333x; 2.1333x over previous
#include <cuda_runtime.h>
#include <cstdint>

// ---------------------------------------------------------------------------
// Shifted-window MSA (Swin SW block).
//   B=8, NSEQ=16384, C=256, P=64, SHIFT=32, NH=8, HD=32, pad=0
// Pipeline:
//   K1: QKV GEMM (tf32 tensor cores, roll on A read)  -> g_qkv [131072 x 768]
//   K2: attention per (window, head)                  -> g_att [131072 x 256]
//   K3: out GEMM  (tf32 tensor cores, roll on C write)-> d_out
// ---------------------------------------------------------------------------

#define BATCH   8
#define NSEQ    16384
#define CDIM    256
#define PWIN    64
#define SHIFT   32
#define NHEADS  8
#define HDIM    32
#define MTOT    (BATCH * NSEQ)     // 131072
#define QKV_N   768
#define NWIN    (MTOT / PWIN)      // 2048
#define WPB     (NSEQ / PWIN)      // 256

__device__ float g_qkv[(size_t)MTOT * QKV_N];   // ~402 MB scratch
__device__ float g_att[(size_t)MTOT * CDIM];    // ~134 MB scratch

// ---------------------------------------------------------------------------
// tf32 helpers
// ---------------------------------------------------------------------------
__device__ __forceinline__ float f2tf32(float x) {
    uint32_t u;
    asm("cvt.rna.tf32.f32 %0, %1;" : "=r"(u) : "f"(x));
    return __uint_as_float(u);
}

__device__ __forceinline__ void mma_tf32(float (&d)[4],
                                         const uint32_t (&a)[4],
                                         const uint32_t (&b)[2]) {
    asm volatile(
        "mma.sync.aligned.m16n8k8.row.col.f32.tf32.tf32.f32 "
        "{%0,%1,%2,%3}, {%4,%5,%6,%7}, {%8,%9}, {%0,%1,%2,%3};"
        : "+f"(d[0]), "+f"(d[1]), "+f"(d[2]), "+f"(d[3])
        : "r"(a[0]), "r"(a[1]), "r"(a[2]), "r"(a[3]), "r"(b[0]), "r"(b[1]));
}

// ---------------------------------------------------------------------------
// TF32 tensor-core GEMM:  C[m,n] = sum_k A'[m,k] * W[n,k] + bias[n]
// BM=128, BN=128, BK=32.  256 threads = 8 warps, warp tile 64x32 (2x4 grid).
// Smem stride 36 floats: fragment-load bank = (4g+tg) mod 32, a permutation
// over the warp -> conflict-free LDS on the hot path.
// ---------------------------------------------------------------------------
template<bool ROLL_A, bool ROLL_OUT>
__global__ void __launch_bounds__(256)
gemm_tf32_kernel(const float* __restrict__ A,
                 const float* __restrict__ W,
                 const float* __restrict__ bias,
                 float* __restrict__ Cout,
                 int Ncols)
{
    __shared__ float As[128][36];   // [m][k]
    __shared__ float Bs[128][36];   // [n][k]

    const int bm = blockIdx.y * 128;
    const int bn = blockIdx.x * 128;

    const int t    = threadIdx.x;
    const int warp = t >> 5;
    const int lane = t & 31;
    const int g    = lane >> 2;     // octet/group id 0..7
    const int tg   = lane & 3;      // thread-in-group 0..3

    const int wm = (warp & 1) * 64; // warp m-base within block
    const int wn = (warp >> 1) * 32;// warp n-base within block

    // ---- gmem load coords: each thread loads 4 float4 per tile per matrix ----
    const int lrow = t >> 3;        // 0..31 (row within chunk group)
    const int lc4  = (t & 7) * 4;   // k offset 0..28

    const float* aptr[4];
    const float* bptr[4];
    int asr[4];
#pragma unroll
    for (int i = 0; i < 4; i++) {
        int row = lrow + i * 32;    // 0..127
        int m  = bm + row;
        int bi = m >> 14, tt = m & 16383;
        int s  = ROLL_A ? ((tt + SHIFT) & 16383) : tt;
        aptr[i] = A + (size_t)((bi << 14) + s) * CDIM + lc4;
        bptr[i] = W + (size_t)(bn + row) * CDIM + lc4;
        asr[i]  = row;
    }

    float acc[4][4][4];
#pragma unroll
    for (int mt = 0; mt < 4; mt++)
#pragma unroll
        for (int nt = 0; nt < 4; nt++)
#pragma unroll
            for (int r = 0; r < 4; r++) acc[mt][nt][r] = 0.0f;

#pragma unroll 1
    for (int kt = 0; kt < 8; kt++) {
        const int k0 = kt * 32;

        float4 av[4], bv[4];
#pragma unroll
        for (int i = 0; i < 4; i++) {
            av[i] = *(const float4*)(aptr[i] + k0);
            bv[i] = *(const float4*)(bptr[i] + k0);
        }

        __syncthreads();   // previous iteration's fragment reads done

#pragma unroll
        for (int i = 0; i < 4; i++) {
            As[asr[i]][lc4 + 0] = f2tf32(av[i].x);
            As[asr[i]][lc4 + 1] = f2tf32(av[i].y);
            As[asr[i]][lc4 + 2] = f2tf32(av[i].z);
            As[asr[i]][lc4 + 3] = f2tf32(av[i].w);
            Bs[asr[i]][lc4 + 0] = f2tf32(bv[i].x);
            Bs[asr[i]][lc4 + 1] = f2tf32(bv[i].y);
            Bs[asr[i]][lc4 + 2] = f2tf32(bv[i].z);
            Bs[asr[i]][lc4 + 3] = f2tf32(bv[i].w);
        }

        __syncthreads();

#pragma unroll
        for (int ks = 0; ks < 4; ks++) {
            const int k = ks * 8;

            uint32_t afr[4][4];
            uint32_t bfr[4][2];
#pragma unroll
            for (int mt = 0; mt < 4; mt++) {
                int r = wm + mt * 16 + g;
                afr[mt][0] = __float_as_uint(As[r    ][k + tg]);
                afr[mt][1] = __float_as_uint(As[r + 8][k + tg]);
                afr[mt][2] = __float_as_uint(As[r    ][k + tg + 4]);
                afr[mt][3] = __float_as_uint(As[r + 8][k + tg + 4]);
            }
#pragma unroll
            for (int nt = 0; nt < 4; nt++) {
                int c = wn + nt * 8 + g;
                bfr[nt][0] = __float_as_uint(Bs[c][k + tg]);
                bfr[nt][1] = __float_as_uint(Bs[c][k + tg + 4]);
            }
#pragma unroll
            for (int mt = 0; mt < 4; mt++)
#pragma unroll
                for (int nt = 0; nt < 4; nt++)
                    mma_tf32(acc[mt][nt], afr[mt], bfr[nt]);
        }
    }

    // ---- epilogue: bias + (optional roll) + float2 stores ----
#pragma unroll
    for (int mt = 0; mt < 4; mt++) {
        int m0 = bm + wm + mt * 16 + g;
        int m1 = m0 + 8;
        int bi0 = m0 >> 14, t0 = m0 & 16383;
        int bi1 = m1 >> 14, t1 = m1 & 16383;
        int d0 = ROLL_OUT ? ((t0 + SHIFT) & 16383) : t0;
        int d1 = ROLL_OUT ? ((t1 + SHIFT) & 16383) : t1;
        float* row0 = Cout + (size_t)((bi0 << 14) + d0) * Ncols;
        float* row1 = Cout + (size_t)((bi1 << 14) + d1) * Ncols;
#pragma unroll
        for (int nt = 0; nt < 4; nt++) {
            int col = bn + wn + nt * 8 + 2 * tg;
            float b0 = bias[col], b1 = bias[col + 1];
            float2 v0 = make_float2(acc[mt][nt][0] + b0, acc[mt][nt][1] + b1);
            float2 v1 = make_float2(acc[mt][nt][2] + b0, acc[mt][nt][3] + b1);
            *(float2*)(row0 + col) = v0;
            *(float2*)(row1 + col) = v1;
        }
    }
}

// ---------------------------------------------------------------------------
// Attention per (window, head). 64 threads = one query row each.
// ---------------------------------------------------------------------------
__global__ void attn_kernel(const float* __restrict__ qkv,
                            const float* __restrict__ rel_pos,
                            float* __restrict__ att)
{
    __shared__ float ks[64][36];
    __shared__ float vs[64][36];
    __shared__ float rel[128];

    const int wi = blockIdx.x;   // 0..2047
    const int h  = blockIdx.y;   // 0..7
    const int i  = threadIdx.x;  // 0..63
    const int mbase = wi * PWIN;

    const float* rowp = qkv + (size_t)(mbase + i) * QKV_N + h * HDIM;

    float q[32];
#pragma unroll
    for (int d4 = 0; d4 < 8; d4++) {
        float4 vq = *(const float4*)(rowp + d4 * 4);
        float4 vk = *(const float4*)(rowp + 256 + d4 * 4);
        float4 vv = *(const float4*)(rowp + 512 + d4 * 4);
        q[d4 * 4 + 0] = vq.x; q[d4 * 4 + 1] = vq.y;
        q[d4 * 4 + 2] = vq.z; q[d4 * 4 + 3] = vq.w;
        *(float4*)&ks[i][d4 * 4] = vk;
        *(float4*)&vs[i][d4 * 4] = vv;
    }
    rel[i] = rel_pos[h * 127 + i];
    if (i < 63) rel[i + 64] = rel_pos[h * 127 + 64 + i];
    __syncthreads();

    const float scale = 0.17677669529663687f;  // 1/sqrt(32)
    const bool lastw = ((wi & (WPB - 1)) == (WPB - 1));

    float acc[32];
#pragma unroll
    for (int d = 0; d < 32; d++) acc[d] = 0.0f;
    float ssum = 0.0f;

#pragma unroll 4
    for (int j = 0; j < 64; j++) {
        float s = 0.0f;
#pragma unroll
        for (int d = 0; d < 32; d++) s += q[d] * ks[j][d];
        s = s * scale + rel[i - j + 63];
        if (lastw && ((i ^ j) & 32)) s = -1e30f;
        float e = __expf(s);
        ssum += e;
#pragma unroll
        for (int d = 0; d < 32; d++) acc[d] += e * vs[j][d];
    }

    const float inv = 1.0f / ssum;
    float* orow = att + (size_t)(mbase + i) * CDIM + h * HDIM;
#pragma unroll
    for (int d4 = 0; d4 < 8; d4++) {
        float4 o;
        o.x = acc[d4 * 4 + 0] * inv; o.y = acc[d4 * 4 + 1] * inv;
        o.z = acc[d4 * 4 + 2] * inv; o.w = acc[d4 * 4 + 3] * inv;
        *(float4*)(orow + d4 * 4) = o;
    }
}

// ---------------------------------------------------------------------------
extern "C" void kernel_launch(void* const* d_in, const int* in_sizes, int n_in,
                              void* d_out, int out_size)
{
    const float* x       = (const float*)d_in[0];
    const float* w_qkv   = (const float*)d_in[1];
    const float* b_qkv   = (const float*)d_in[2];
    const float* rel_pos = (const float*)d_in[3];
    const float* w_out   = (const float*)d_in[4];
    const float* b_out   = (const float*)d_in[5];
    float* out = (float*)d_out;

    float* qkvp = nullptr;
    float* attp = nullptr;
    cudaGetSymbolAddress((void**)&qkvp, g_qkv);
    cudaGetSymbolAddress((void**)&attp, g_att);

    // K1: QKV projection with input roll.
    {
        dim3 grid(QKV_N / 128, MTOT / 128);
        gemm_tf32_kernel<true, false><<<grid, 256>>>(x, w_qkv, b_qkv, qkvp, QKV_N);
    }
    // K2: windowed attention.
    {
        dim3 grid(NWIN, NHEADS);
        attn_kernel<<<grid, 64>>>(qkvp, rel_pos, attp);
    }
    // K3: output projection with output roll.
    {
        dim3 grid(CDIM / 128, MTOT / 128);
        gemm_tf32_kernel<false, true><<<grid, 256>>>(attp, w_out, b_out, out, CDIM);
    }
}

// round 3
// speedup vs baseline: 3.0334x; 1.4220x over previous
#include <cuda_runtime.h>
#include <cstdint>

// ---------------------------------------------------------------------------
// Shifted-window MSA. B=8, NSEQ=16384, C=256, P=64, SHIFT=32, NH=8, HD=32.
//   K1: QKV GEMM (tf32 mma + ldmatrix, roll on A read) -> g_qkv
//   K2: attention (tf32 mma, per window-head)          -> g_att
//   K3: out GEMM  (tf32 mma + ldmatrix, roll on write) -> d_out
// ---------------------------------------------------------------------------

#define BATCH   8
#define NSEQ    16384
#define CDIM    256
#define PWIN    64
#define SHIFT   32
#define NHEADS  8
#define HDIM    32
#define MTOT    (BATCH * NSEQ)
#define QKV_N   768
#define NWIN    (MTOT / PWIN)      // 2048
#define WPB     (NSEQ / PWIN)      // 256

__device__ float g_qkv[(size_t)MTOT * QKV_N];
__device__ float g_att[(size_t)MTOT * CDIM];

// ---------------------------------------------------------------------------
__device__ __forceinline__ float f2tf32(float x) {
    uint32_t u;
    asm("cvt.rna.tf32.f32 %0, %1;" : "=r"(u) : "f"(x));
    return __uint_as_float(u);
}

__device__ __forceinline__ void mma_tf32(float (&d)[4],
                                         const uint32_t (&a)[4],
                                         const uint32_t (&b)[2]) {
    asm volatile(
        "mma.sync.aligned.m16n8k8.row.col.f32.tf32.tf32.f32 "
        "{%0,%1,%2,%3}, {%4,%5,%6,%7}, {%8,%9}, {%0,%1,%2,%3};"
        : "+f"(d[0]), "+f"(d[1]), "+f"(d[2]), "+f"(d[3])
        : "r"(a[0]), "r"(a[1]), "r"(a[2]), "r"(a[3]), "r"(b[0]), "r"(b[1]));
}

__device__ __forceinline__ void ldsm_x4(uint32_t (&r)[4], uint32_t addr) {
    asm volatile("ldmatrix.sync.aligned.m8n8.x4.shared.b16 {%0,%1,%2,%3}, [%4];"
        : "=r"(r[0]), "=r"(r[1]), "=r"(r[2]), "=r"(r[3]) : "r"(addr));
}

__device__ __forceinline__ uint32_t smem_u32(const void* p) {
    return (uint32_t)__cvta_generic_to_shared(p);
}

// ---------------------------------------------------------------------------
// TF32 GEMM with ldmatrix fragment loads.
// BM=BN=128, BK=32, 256 threads = 8 warps, warp tile 64x32.
// ---------------------------------------------------------------------------
template<bool ROLL_A, bool ROLL_OUT>
__global__ void __launch_bounds__(256)
gemm_tf32_kernel(const float* __restrict__ A,
                 const float* __restrict__ W,
                 const float* __restrict__ bias,
                 float* __restrict__ Cout,
                 int Ncols)
{
    __shared__ float As[128][36];
    __shared__ float Bs[128][36];

    const int bm = blockIdx.y * 128;
    const int bn = blockIdx.x * 128;

    const int t    = threadIdx.x;
    const int warp = t >> 5;
    const int lane = t & 31;
    const int g    = lane >> 2;
    const int tg   = lane & 3;

    const int wm = (warp & 1) * 64;
    const int wn = (warp >> 1) * 32;

    const int lrow = t >> 3;
    const int lc4  = (t & 7) * 4;

    const float* aptr[4];
    const float* bptr[4];
    int asr[4];
#pragma unroll
    for (int i = 0; i < 4; i++) {
        int row = lrow + i * 32;
        int m  = bm + row;
        int bi = m >> 14, tt = m & 16383;
        int s  = ROLL_A ? ((tt + SHIFT) & 16383) : tt;
        aptr[i] = A + (size_t)((bi << 14) + s) * CDIM + lc4;
        bptr[i] = W + (size_t)(bn + row) * CDIM + lc4;
        asr[i]  = row;
    }

    // ldmatrix base addresses (k = 0)
    uint32_t aAddr[4], bAddr[2];
#pragma unroll
    for (int mt = 0; mt < 4; mt++)
        aAddr[mt] = smem_u32(&As[wm + mt * 16 + (lane & 15)][(lane >> 4) * 4]);
#pragma unroll
    for (int ntp = 0; ntp < 2; ntp++)
        bAddr[ntp] = smem_u32(&Bs[wn + ntp * 16 + (lane & 7) + ((lane >> 4) << 3)]
                                 [((lane >> 3) & 1) * 4]);

    float acc[4][4][4];
#pragma unroll
    for (int mt = 0; mt < 4; mt++)
#pragma unroll
        for (int nt = 0; nt < 4; nt++)
#pragma unroll
            for (int r = 0; r < 4; r++) acc[mt][nt][r] = 0.0f;

#pragma unroll 1
    for (int kt = 0; kt < 8; kt++) {
        const int k0 = kt * 32;

        float4 av[4], bv[4];
#pragma unroll
        for (int i = 0; i < 4; i++) {
            av[i] = *(const float4*)(aptr[i] + k0);
            bv[i] = *(const float4*)(bptr[i] + k0);
        }

        __syncthreads();

#pragma unroll
        for (int i = 0; i < 4; i++) {
            *(float4*)&As[asr[i]][lc4] = make_float4(
                f2tf32(av[i].x), f2tf32(av[i].y), f2tf32(av[i].z), f2tf32(av[i].w));
            *(float4*)&Bs[asr[i]][lc4] = make_float4(
                f2tf32(bv[i].x), f2tf32(bv[i].y), f2tf32(bv[i].z), f2tf32(bv[i].w));
        }

        __syncthreads();

#pragma unroll
        for (int ks = 0; ks < 4; ks++) {
            const uint32_t koff = ks * 32;  // 8 floats = 32 bytes
            uint32_t afr[4][4], bp[2][4];
#pragma unroll
            for (int mt = 0; mt < 4; mt++) ldsm_x4(afr[mt], aAddr[mt] + koff);
#pragma unroll
            for (int ntp = 0; ntp < 2; ntp++) ldsm_x4(bp[ntp], bAddr[ntp] + koff);
#pragma unroll
            for (int mt = 0; mt < 4; mt++)
#pragma unroll
                for (int nt = 0; nt < 4; nt++) {
                    uint32_t bfr[2] = { bp[nt >> 1][(nt & 1) * 2],
                                        bp[nt >> 1][(nt & 1) * 2 + 1] };
                    mma_tf32(acc[mt][nt], afr[mt], bfr);
                }
        }
    }

#pragma unroll
    for (int mt = 0; mt < 4; mt++) {
        int m0 = bm + wm + mt * 16 + g;
        int m1 = m0 + 8;
        int bi0 = m0 >> 14, t0 = m0 & 16383;
        int bi1 = m1 >> 14, t1 = m1 & 16383;
        int d0 = ROLL_OUT ? ((t0 + SHIFT) & 16383) : t0;
        int d1 = ROLL_OUT ? ((t1 + SHIFT) & 16383) : t1;
        float* row0 = Cout + (size_t)((bi0 << 14) + d0) * Ncols;
        float* row1 = Cout + (size_t)((bi1 << 14) + d1) * Ncols;
#pragma unroll
        for (int nt = 0; nt < 4; nt++) {
            int col = bn + wn + nt * 8 + 2 * tg;
            float b0 = bias[col], b1 = bias[col + 1];
            *(float2*)(row0 + col) = make_float2(acc[mt][nt][0] + b0, acc[mt][nt][1] + b1);
            *(float2*)(row1 + col) = make_float2(acc[mt][nt][2] + b0, acc[mt][nt][3] + b1);
        }
    }
}

// ---------------------------------------------------------------------------
// Tensor-core attention. Block = (window, head), 128 threads = 4 warps.
// Warp w handles query rows [16w, 16w+16).
//   S (16x64) = Q(16x32) K^T           (A = Q from smem [i][d], B = K [j][d])
//   P = exp(S*scale + rel) (mask on last window), rowsum via shfl
//   O^T (32x16) = V^T(32x64) P^T       (A = VT [d][j], B = P [i][j])
// Epilogue: O^T frags -> smem (reuse P) -> normalized coalesced writes.
// ---------------------------------------------------------------------------
__global__ void __launch_bounds__(128)
attn_mma_kernel(const float* __restrict__ qkv,
                const float* __restrict__ rel_pos,
                float* __restrict__ att)
{
    __shared__ float Qs[64][36];
    __shared__ float Ks[64][36];
    __shared__ float VT[32][68];
    __shared__ float Ps[64][68];
    __shared__ float rels[128];
    __shared__ float sinv[64];

    const int wi = blockIdx.x;
    const int h  = blockIdx.y;
    const int tid  = threadIdx.x;
    const int w    = tid >> 5;
    const int lane = tid & 31;
    const int g    = lane >> 2;
    const int tg   = lane & 3;
    const int mbase = wi * PWIN;
    const bool lastw = ((wi & (WPB - 1)) == (WPB - 1));

    // ---- stage Q, K ([j][d], tf32) and V^T ([d][j], tf32) ----
#pragma unroll
    for (int it = 0; it < 4; it++) {
        int idx = tid + it * 128;          // 0..511
        int j = idx >> 3, d4 = (idx & 7) * 4;
        const float* base = qkv + (size_t)(mbase + j) * QKV_N + h * HDIM + d4;
        float4 q4 = *(const float4*)(base);
        float4 k4 = *(const float4*)(base + 256);
        float4 v4 = *(const float4*)(base + 512);
        *(float4*)&Qs[j][d4] = make_float4(f2tf32(q4.x), f2tf32(q4.y),
                                           f2tf32(q4.z), f2tf32(q4.w));
        *(float4*)&Ks[j][d4] = make_float4(f2tf32(k4.x), f2tf32(k4.y),
                                           f2tf32(k4.z), f2tf32(k4.w));
        VT[d4 + 0][j] = f2tf32(v4.x);
        VT[d4 + 1][j] = f2tf32(v4.y);
        VT[d4 + 2][j] = f2tf32(v4.z);
        VT[d4 + 3][j] = f2tf32(v4.w);
    }
    if (tid < 127) rels[tid] = rel_pos[h * 127 + tid];
    __syncthreads();

    // ---- Q fragments (held in regs) ----
    uint32_t qfr[4][4];
    {
        uint32_t qa = smem_u32(&Qs[w * 16 + (lane & 15)][(lane >> 4) * 4]);
#pragma unroll
        for (int ks = 0; ks < 4; ks++) ldsm_x4(qfr[ks], qa + ks * 32);
    }

    // ---- S = Q K^T ----
    float sfr[8][4];
#pragma unroll
    for (int nt = 0; nt < 8; nt++)
#pragma unroll
        for (int r = 0; r < 4; r++) sfr[nt][r] = 0.0f;

    {
        uint32_t kb = smem_u32(&Ks[(lane & 7) + ((lane >> 4) << 3)][((lane >> 3) & 1) * 4]);
#pragma unroll
        for (int ks = 0; ks < 4; ks++) {
#pragma unroll
            for (int ntp = 0; ntp < 4; ntp++) {
                uint32_t bb[4];
                ldsm_x4(bb, kb + (uint32_t)(ntp * 16 * 36 * 4) + ks * 32);
                uint32_t b0[2] = { bb[0], bb[1] };
                uint32_t b1[2] = { bb[2], bb[3] };
                mma_tf32(sfr[ntp * 2],     qfr[ks], b0);
                mma_tf32(sfr[ntp * 2 + 1], qfr[ks], b1);
            }
        }
    }

    // ---- softmax (no max-subtraction: logits are tiny), mask, P -> smem ----
    const float scale = 0.17677669529663687f;
    const int i0 = w * 16 + g;
    const int i1 = i0 + 8;
    const int myside = w >> 1;               // (i & 32) != 0
    float sum0 = 0.0f, sum1 = 0.0f;
#pragma unroll
    for (int nt = 0; nt < 8; nt++) {
        int j0 = nt * 8 + 2 * tg;
        float e00, e01, e10, e11;
        if (lastw && ((nt >> 2) != myside)) {
            e00 = e01 = e10 = e11 = 0.0f;
        } else {
            e00 = __expf(sfr[nt][0] * scale + rels[i0 - j0 + 63]);
            e01 = __expf(sfr[nt][1] * scale + rels[i0 - j0 + 62]);
            e10 = __expf(sfr[nt][2] * scale + rels[i1 - j0 + 63]);
            e11 = __expf(sfr[nt][3] * scale + rels[i1 - j0 + 62]);
        }
        sum0 += e00 + e01;
        sum1 += e10 + e11;
        *(float2*)&Ps[i0][j0] = make_float2(f2tf32(e00), f2tf32(e01));
        *(float2*)&Ps[i1][j0] = make_float2(f2tf32(e10), f2tf32(e11));
    }
    sum0 += __shfl_xor_sync(0xffffffffu, sum0, 1);
    sum0 += __shfl_xor_sync(0xffffffffu, sum0, 2);
    sum1 += __shfl_xor_sync(0xffffffffu, sum1, 1);
    sum1 += __shfl_xor_sync(0xffffffffu, sum1, 2);
    if (tg == 0) { sinv[i0] = 1.0f / sum0; sinv[i1] = 1.0f / sum1; }
    __syncwarp();

    // ---- O^T = V^T x P^T ----
    float ofr[2][2][4];
#pragma unroll
    for (int mt = 0; mt < 2; mt++)
#pragma unroll
        for (int nt = 0; nt < 2; nt++)
#pragma unroll
            for (int r = 0; r < 4; r++) ofr[mt][nt][r] = 0.0f;

    {
        uint32_t va = smem_u32(&VT[(lane & 15)][(lane >> 4) * 4]);
        uint32_t pb = smem_u32(&Ps[w * 16 + (lane & 7) + ((lane >> 4) << 3)]
                                  [((lane >> 3) & 1) * 4]);
#pragma unroll
        for (int ks = 0; ks < 8; ks++) {
            uint32_t a0[4], a1[4], bb[4];
            ldsm_x4(a0, va + ks * 32);
            ldsm_x4(a1, va + (uint32_t)(16 * 68 * 4) + ks * 32);
            ldsm_x4(bb, pb + ks * 32);
            uint32_t b0[2] = { bb[0], bb[1] };
            uint32_t b1[2] = { bb[2], bb[3] };
            mma_tf32(ofr[0][0], a0, b0);
            mma_tf32(ofr[0][1], a0, b1);
            mma_tf32(ofr[1][0], a1, b0);
            mma_tf32(ofr[1][1], a1, b1);
        }
    }

    // ---- transpose via smem (reuse Ps rows we own), normalize, write ----
#pragma unroll
    for (int mt = 0; mt < 2; mt++)
#pragma unroll
        for (int nt = 0; nt < 2; nt++) {
            int d = mt * 16 + g;
            int i = w * 16 + nt * 8 + 2 * tg;
            Ps[i][d]         = ofr[mt][nt][0];
            Ps[i + 1][d]     = ofr[mt][nt][1];
            Ps[i][d + 8]     = ofr[mt][nt][2];
            Ps[i + 1][d + 8] = ofr[mt][nt][3];
        }
    __syncthreads();

#pragma unroll
    for (int it = 0; it < 4; it++) {
        int idx = tid + it * 128;
        int i = idx >> 3, d4 = (idx & 7) * 4;
        float inv = sinv[i];
        float4 v = *(float4*)&Ps[i][d4];
        v.x *= inv; v.y *= inv; v.z *= inv; v.w *= inv;
        *(float4*)(att + (size_t)(mbase + i) * CDIM + h * HDIM + d4) = v;
    }
}

// ---------------------------------------------------------------------------
extern "C" void kernel_launch(void* const* d_in, const int* in_sizes, int n_in,
                              void* d_out, int out_size)
{
    const float* x       = (const float*)d_in[0];
    const float* w_qkv   = (const float*)d_in[1];
    const float* b_qkv   = (const float*)d_in[2];
    const float* rel_pos = (const float*)d_in[3];
    const float* w_out   = (const float*)d_in[4];
    const float* b_out   = (const float*)d_in[5];
    float* out = (float*)d_out;

    float* qkvp = nullptr;
    float* attp = nullptr;
    cudaGetSymbolAddress((void**)&qkvp, g_qkv);
    cudaGetSymbolAddress((void**)&attp, g_att);

    {
        dim3 grid(QKV_N / 128, MTOT / 128);
        gemm_tf32_kernel<true, false><<<grid, 256>>>(x, w_qkv, b_qkv, qkvp, QKV_N);
    }
    {
        dim3 grid(NWIN, NHEADS);
        attn_mma_kernel<<<grid, 128>>>(qkvp, rel_pos, attp);
    }
    {
        dim3 grid(CDIM / 128, MTOT / 128);
        gemm_tf32_kernel<false, true><<<grid, 256>>>(attp, w_out, b_out, out, CDIM);
    }
}

// round 7
// speedup vs baseline: 3.8209x; 1.2596x over previous
#include <cuda_runtime.h>
#include <cuda_fp16.h>
#include <cstdint>

// ---------------------------------------------------------------------------
// Shifted-window MSA. B=8, NSEQ=16384, C=256, P=64, SHIFT=32, NH=8, HD=32.
//   K0: cvt x(rolled)->fp16, w_qkv->fp16, w_out->fp16
//   K1: QKV GEMM (mma.sync m16n8k16 fp16->fp32)     -> g_qkv (fp32)
//   K2: attention (mma.sync tf32, per window-head)  -> g_att (fp16)
//   K3: out GEMM (fp16 mma, roll on write)          -> d_out (fp32)
// NOTE: tcgen05 is unusable here (harness compiles .target sm_103, no 'a').
// Re-run of R5 source: prior failure was "container failed twice" with no
// compile/runtime error — consistent with infra flake, not kernel fault.
// ---------------------------------------------------------------------------

#define BATCH   8
#define NSEQ    16384
#define CDIM    256
#define PWIN    64
#define SHIFT   32
#define NHEADS  8
#define HDIM    32
#define MTOT    (BATCH * NSEQ)
#define QKV_N   768
#define NWIN    (MTOT / PWIN)
#define WPB     (NSEQ / PWIN)

__device__ float  g_qkv  [(size_t)MTOT * QKV_N];   // fp32 (attention input)
__device__ __half g_att  [(size_t)MTOT * CDIM];    // fp16 (K3 input)
__device__ __half g_xh   [(size_t)MTOT * CDIM];    // fp16 rolled x
__device__ __half g_wqkvh[(size_t)QKV_N * CDIM];
__device__ __half g_wouth[(size_t)CDIM * CDIM];

// ---------------------------------------------------------------------------
__device__ __forceinline__ float f2tf32(float x) {
    uint32_t u;
    asm("cvt.rna.tf32.f32 %0, %1;" : "=r"(u) : "f"(x));
    return __uint_as_float(u);
}
__device__ __forceinline__ uint32_t smem_u32(const void* p) {
    return (uint32_t)__cvta_generic_to_shared(p);
}

__device__ __forceinline__ void mma_f16(float (&d)[4],
                                        const uint32_t (&a)[4],
                                        const uint32_t (&b)[2]) {
    asm volatile(
        "mma.sync.aligned.m16n8k16.row.col.f32.f16.f16.f32 "
        "{%0,%1,%2,%3}, {%4,%5,%6,%7}, {%8,%9}, {%0,%1,%2,%3};"
        : "+f"(d[0]), "+f"(d[1]), "+f"(d[2]), "+f"(d[3])
        : "r"(a[0]), "r"(a[1]), "r"(a[2]), "r"(a[3]), "r"(b[0]), "r"(b[1]));
}

__device__ __forceinline__ void mma_tf32(float (&d)[4],
                                         const uint32_t (&a)[4],
                                         const uint32_t (&b)[2]) {
    asm volatile(
        "mma.sync.aligned.m16n8k8.row.col.f32.tf32.tf32.f32 "
        "{%0,%1,%2,%3}, {%4,%5,%6,%7}, {%8,%9}, {%0,%1,%2,%3};"
        : "+f"(d[0]), "+f"(d[1]), "+f"(d[2]), "+f"(d[3])
        : "r"(a[0]), "r"(a[1]), "r"(a[2]), "r"(a[3]), "r"(b[0]), "r"(b[1]));
}
__device__ __forceinline__ void ldsm_x4(uint32_t (&r)[4], uint32_t addr) {
    asm volatile("ldmatrix.sync.aligned.m8n8.x4.shared.b16 {%0,%1,%2,%3}, [%4];"
        : "=r"(r[0]), "=r"(r[1]), "=r"(r[2]), "=r"(r[3]) : "r"(addr));
}

// ---------------------------------------------------------------------------
// FP16 GEMM: C[m,n] = sum_k A[m,k]*W[n,k] + bias[n]   (A, W fp16; C fp32)
// BM=BN=128, BK=64, 256 threads = 8 warps, warp tile 64x32.
// Smem stride 72 halves: fragment LDS.32 bank = (4g+tg) mod 32 — conflict-free;
// 144-byte row stride keeps 16B chunk stores aligned.
// ---------------------------------------------------------------------------
#define HBK 64

template<bool ROLL_OUT>
__global__ void __launch_bounds__(256, 2)
gemm_f16_kernel(const __half* __restrict__ A,
                const __half* __restrict__ W,
                const float* __restrict__ bias,
                float* __restrict__ Cout,
                int Ncols)
{
    __shared__ __half As[128][72];
    __shared__ __half Bs[128][72];

    const int bm = blockIdx.y * 128;
    const int bn = blockIdx.x * 128;

    const int t    = threadIdx.x;
    const int warp = t >> 5;
    const int lane = t & 31;
    const int g    = lane >> 2;
    const int tg   = lane & 3;

    const int wm = (warp & 1) * 64;
    const int wn = (warp >> 1) * 32;

    // gmem load map: 128 rows x 8 chunks(16B) per matrix, 4 chunks/thread
    int arow[4], ac[4];
#pragma unroll
    for (int i = 0; i < 4; i++) {
        int id = t + i * 256;
        arow[i] = id >> 3;
        ac[i]   = id & 7;
    }
    const __half* Ab = A + (size_t)bm * CDIM;
    const __half* Wb = W + (size_t)bn * CDIM;

    float acc[4][4][4];
#pragma unroll
    for (int mt = 0; mt < 4; mt++)
#pragma unroll
        for (int nt = 0; nt < 4; nt++)
#pragma unroll
            for (int r = 0; r < 4; r++) acc[mt][nt][r] = 0.0f;

#pragma unroll 1
    for (int kt = 0; kt < 4; kt++) {
        const int k0 = kt * HBK;

        uint4 av[4], bv[4];
#pragma unroll
        for (int i = 0; i < 4; i++) {
            av[i] = *(const uint4*)(Ab + (size_t)arow[i] * CDIM + k0 + ac[i] * 8);
            bv[i] = *(const uint4*)(Wb + (size_t)arow[i] * CDIM + k0 + ac[i] * 8);
        }

        __syncthreads();   // previous iteration's fragment reads done
#pragma unroll
        for (int i = 0; i < 4; i++) {
            *(uint4*)&As[arow[i]][ac[i] * 8] = av[i];
            *(uint4*)&Bs[arow[i]][ac[i] * 8] = bv[i];
        }
        __syncthreads();

#pragma unroll
        for (int ks = 0; ks < 4; ks++) {
            const int k = ks * 16;
            uint32_t afr[4][4], bfr[4][2];
#pragma unroll
            for (int mt = 0; mt < 4; mt++) {
                int r = wm + mt * 16 + g;
                afr[mt][0] = *(const uint32_t*)&As[r    ][k + 2 * tg];
                afr[mt][1] = *(const uint32_t*)&As[r + 8][k + 2 * tg];
                afr[mt][2] = *(const uint32_t*)&As[r    ][k + 2 * tg + 8];
                afr[mt][3] = *(const uint32_t*)&As[r + 8][k + 2 * tg + 8];
            }
#pragma unroll
            for (int nt = 0; nt < 4; nt++) {
                int n = wn + nt * 8 + g;
                bfr[nt][0] = *(const uint32_t*)&Bs[n][k + 2 * tg];
                bfr[nt][1] = *(const uint32_t*)&Bs[n][k + 2 * tg + 8];
            }
#pragma unroll
            for (int mt = 0; mt < 4; mt++)
#pragma unroll
                for (int nt = 0; nt < 4; nt++)
                    mma_f16(acc[mt][nt], afr[mt], bfr[nt]);
        }
    }

    // ---- epilogue: bias + optional output roll, float2 stores ----
#pragma unroll
    for (int mt = 0; mt < 4; mt++) {
        int m0 = bm + wm + mt * 16 + g;
        int m1 = m0 + 8;
        int bi0 = m0 >> 14, t0 = m0 & 16383;
        int bi1 = m1 >> 14, t1 = m1 & 16383;
        int d0 = ROLL_OUT ? ((t0 + SHIFT) & 16383) : t0;
        int d1 = ROLL_OUT ? ((t1 + SHIFT) & 16383) : t1;
        float* row0 = Cout + (size_t)((bi0 << 14) + d0) * Ncols;
        float* row1 = Cout + (size_t)((bi1 << 14) + d1) * Ncols;
#pragma unroll
        for (int nt = 0; nt < 4; nt++) {
            int col = bn + wn + nt * 8 + 2 * tg;
            float b0 = bias[col], b1 = bias[col + 1];
            *(float2*)(row0 + col) = make_float2(acc[mt][nt][0] + b0, acc[mt][nt][1] + b1);
            *(float2*)(row1 + col) = make_float2(acc[mt][nt][2] + b0, acc[mt][nt][3] + b1);
        }
    }
}

// ---------------------------------------------------------------------------
// cvt pre-passes: fp32 -> fp16
// ---------------------------------------------------------------------------
__global__ void cvt_roll_h_kernel(const float* __restrict__ x, __half* __restrict__ xh)
{
    size_t i4 = (size_t)blockIdx.x * 256 + threadIdx.x;
    size_t fi = i4 * 4;
    int m = (int)(fi >> 8);
    int c = (int)(fi & 255);
    int bi = m >> 14, t = m & 16383;
    int s = (t + SHIFT) & 16383;
    float4 v = *(const float4*)(x + (size_t)((bi << 14) + s) * CDIM + c);
    __half2 h0 = __floats2half2_rn(v.x, v.y);
    __half2 h1 = __floats2half2_rn(v.z, v.w);
    *(uint2*)(xh + fi) = make_uint2(*(uint32_t*)&h0, *(uint32_t*)&h1);
}

__global__ void cvt_h_kernel(const float* __restrict__ src, __half* __restrict__ dst, int n4)
{
    int i = blockIdx.x * 256 + threadIdx.x;
    if (i < n4) {
        float4 v = *(const float4*)(src + (size_t)i * 4);
        __half2 h0 = __floats2half2_rn(v.x, v.y);
        __half2 h1 = __floats2half2_rn(v.z, v.w);
        *(uint2*)(dst + (size_t)i * 4) = make_uint2(*(uint32_t*)&h0, *(uint32_t*)&h1);
    }
}

// ---------------------------------------------------------------------------
// Attention (mma.sync tf32), proven correct in R2/R3; epilogue emits fp16.
// ---------------------------------------------------------------------------
__global__ void __launch_bounds__(128)
attn_mma_kernel(const float* __restrict__ qkv,
                const float* __restrict__ rel_pos,
                __half* __restrict__ att)
{
    __shared__ float Qs[64][36];
    __shared__ float Ks[64][36];
    __shared__ float VT[32][68];
    __shared__ float Ps[64][68];
    __shared__ float rels[128];
    __shared__ float sinv[64];

    const int wi = blockIdx.x;
    const int h  = blockIdx.y;
    const int tid  = threadIdx.x;
    const int w    = tid >> 5;
    const int lane = tid & 31;
    const int g    = lane >> 2;
    const int tg   = lane & 3;
    const int mbase = wi * PWIN;
    const bool lastw = ((wi & (WPB - 1)) == (WPB - 1));

#pragma unroll
    for (int it = 0; it < 4; it++) {
        int idx = tid + it * 128;
        int j = idx >> 3, d4 = (idx & 7) * 4;
        const float* base = qkv + (size_t)(mbase + j) * QKV_N + h * HDIM + d4;
        float4 q4 = *(const float4*)(base);
        float4 k4 = *(const float4*)(base + 256);
        float4 v4 = *(const float4*)(base + 512);
        *(float4*)&Qs[j][d4] = make_float4(f2tf32(q4.x), f2tf32(q4.y),
                                           f2tf32(q4.z), f2tf32(q4.w));
        *(float4*)&Ks[j][d4] = make_float4(f2tf32(k4.x), f2tf32(k4.y),
                                           f2tf32(k4.z), f2tf32(k4.w));
        VT[d4 + 0][j] = f2tf32(v4.x);
        VT[d4 + 1][j] = f2tf32(v4.y);
        VT[d4 + 2][j] = f2tf32(v4.z);
        VT[d4 + 3][j] = f2tf32(v4.w);
    }
    if (tid < 127) rels[tid] = rel_pos[h * 127 + tid];
    __syncthreads();

    uint32_t qfr[4][4];
    {
        uint32_t qa = smem_u32(&Qs[w * 16 + (lane & 15)][(lane >> 4) * 4]);
#pragma unroll
        for (int ks = 0; ks < 4; ks++) ldsm_x4(qfr[ks], qa + ks * 32);
    }

    float sfr[8][4];
#pragma unroll
    for (int nt = 0; nt < 8; nt++)
#pragma unroll
        for (int r = 0; r < 4; r++) sfr[nt][r] = 0.0f;

    {
        uint32_t kb = smem_u32(&Ks[(lane & 7) + ((lane >> 4) << 3)][((lane >> 3) & 1) * 4]);
#pragma unroll
        for (int ks = 0; ks < 4; ks++) {
#pragma unroll
            for (int ntp = 0; ntp < 4; ntp++) {
                uint32_t bb[4];
                ldsm_x4(bb, kb + (uint32_t)(ntp * 16 * 36 * 4) + ks * 32);
                uint32_t b0[2] = { bb[0], bb[1] };
                uint32_t b1[2] = { bb[2], bb[3] };
                mma_tf32(sfr[ntp * 2],     qfr[ks], b0);
                mma_tf32(sfr[ntp * 2 + 1], qfr[ks], b1);
            }
        }
    }

    const float scale = 0.17677669529663687f;
    const int i0 = w * 16 + g;
    const int i1 = i0 + 8;
    const int myside = w >> 1;
    float sum0 = 0.0f, sum1 = 0.0f;
#pragma unroll
    for (int nt = 0; nt < 8; nt++) {
        int j0 = nt * 8 + 2 * tg;
        float e00, e01, e10, e11;
        if (lastw && ((nt >> 2) != myside)) {
            e00 = e01 = e10 = e11 = 0.0f;
        } else {
            e00 = __expf(sfr[nt][0] * scale + rels[i0 - j0 + 63]);
            e01 = __expf(sfr[nt][1] * scale + rels[i0 - j0 + 62]);
            e10 = __expf(sfr[nt][2] * scale + rels[i1 - j0 + 63]);
            e11 = __expf(sfr[nt][3] * scale + rels[i1 - j0 + 62]);
        }
        sum0 += e00 + e01;
        sum1 += e10 + e11;
        *(float2*)&Ps[i0][j0] = make_float2(f2tf32(e00), f2tf32(e01));
        *(float2*)&Ps[i1][j0] = make_float2(f2tf32(e10), f2tf32(e11));
    }
    sum0 += __shfl_xor_sync(0xffffffffu, sum0, 1);
    sum0 += __shfl_xor_sync(0xffffffffu, sum0, 2);
    sum1 += __shfl_xor_sync(0xffffffffu, sum1, 1);
    sum1 += __shfl_xor_sync(0xffffffffu, sum1, 2);
    if (tg == 0) { sinv[i0] = 1.0f / sum0; sinv[i1] = 1.0f / sum1; }
    __syncwarp();

    float ofr[2][2][4];
#pragma unroll
    for (int mt = 0; mt < 2; mt++)
#pragma unroll
        for (int nt = 0; nt < 2; nt++)
#pragma unroll
            for (int r = 0; r < 4; r++) ofr[mt][nt][r] = 0.0f;

    {
        uint32_t va = smem_u32(&VT[(lane & 15)][(lane >> 4) * 4]);
        uint32_t pb = smem_u32(&Ps[w * 16 + (lane & 7) + ((lane >> 4) << 3)]
                                  [((lane >> 3) & 1) * 4]);
#pragma unroll
        for (int ks = 0; ks < 8; ks++) {
            uint32_t a0[4], a1[4], bb[4];
            ldsm_x4(a0, va + ks * 32);
            ldsm_x4(a1, va + (uint32_t)(16 * 68 * 4) + ks * 32);
            ldsm_x4(bb, pb + ks * 32);
            uint32_t b0[2] = { bb[0], bb[1] };
            uint32_t b1[2] = { bb[2], bb[3] };
            mma_tf32(ofr[0][0], a0, b0);
            mma_tf32(ofr[0][1], a0, b1);
            mma_tf32(ofr[1][0], a1, b0);
            mma_tf32(ofr[1][1], a1, b1);
        }
    }

#pragma unroll
    for (int mt = 0; mt < 2; mt++)
#pragma unroll
        for (int nt = 0; nt < 2; nt++) {
            int d = mt * 16 + g;
            int i = w * 16 + nt * 8 + 2 * tg;
            Ps[i][d]         = ofr[mt][nt][0];
            Ps[i + 1][d]     = ofr[mt][nt][1];
            Ps[i][d + 8]     = ofr[mt][nt][2];
            Ps[i + 1][d + 8] = ofr[mt][nt][3];
        }
    __syncthreads();

#pragma unroll
    for (int it = 0; it < 4; it++) {
        int idx = tid + it * 128;
        int i = idx >> 3, d4 = (idx & 7) * 4;
        float inv = sinv[i];
        float4 v = *(float4*)&Ps[i][d4];
        __half2 h0 = __floats2half2_rn(v.x * inv, v.y * inv);
        __half2 h1 = __floats2half2_rn(v.z * inv, v.w * inv);
        *(uint2*)(att + (size_t)(mbase + i) * CDIM + h * HDIM + d4) =
            make_uint2(*(uint32_t*)&h0, *(uint32_t*)&h1);
    }
}

// ---------------------------------------------------------------------------
extern "C" void kernel_launch(void* const* d_in, const int* in_sizes, int n_in,
                              void* d_out, int out_size)
{
    const float* x       = (const float*)d_in[0];
    const float* w_qkv   = (const float*)d_in[1];
    const float* b_qkv   = (const float*)d_in[2];
    const float* rel_pos = (const float*)d_in[3];
    const float* w_out   = (const float*)d_in[4];
    const float* b_out   = (const float*)d_in[5];
    float* out = (float*)d_out;

    float  *qkvp;
    __half *attp, *xhp, *wqkvp, *woutp;
    cudaGetSymbolAddress((void**)&qkvp,  g_qkv);
    cudaGetSymbolAddress((void**)&attp,  g_att);
    cudaGetSymbolAddress((void**)&xhp,   g_xh);
    cudaGetSymbolAddress((void**)&wqkvp, g_wqkvh);
    cudaGetSymbolAddress((void**)&woutp, g_wouth);

    // K0: fp16 pre-conversion (roll folded into x copy)
    cvt_roll_h_kernel<<<(MTOT * CDIM / 4) / 256, 256>>>(x, xhp);
    cvt_h_kernel<<<(QKV_N * CDIM / 4 + 255) / 256, 256>>>(w_qkv, wqkvp, QKV_N * CDIM / 4);
    cvt_h_kernel<<<(CDIM * CDIM / 4 + 255) / 256, 256>>>(w_out, woutp, CDIM * CDIM / 4);

    // K1: QKV projection (fp16 tensor cores)
    {
        dim3 grid(QKV_N / 128, MTOT / 128);   // (6, 1024)
        gemm_f16_kernel<false><<<grid, 256>>>(xhp, wqkvp, b_qkv, qkvp, QKV_N);
    }
    // K2: windowed attention
    {
        dim3 grid(NWIN, NHEADS);
        attn_mma_kernel<<<grid, 128>>>(qkvp, rel_pos, attp);
    }
    // K3: output projection (fp16 tensor cores, roll on write)
    {
        dim3 grid(CDIM / 128, MTOT / 128);    // (2, 1024)
        gemm_f16_kernel<true><<<grid, 256>>>(attp, woutp, b_out, out, CDIM);
    }
}

// round 8
// speedup vs baseline: 4.2917x; 1.1232x over previous
#include <cuda_runtime.h>
#include <cuda_fp16.h>
#include <cstdint>

// ---------------------------------------------------------------------------
// Shifted-window MSA. B=8, NSEQ=16384, C=256, P=64, SHIFT=32, NH=8, HD=32.
//   K0: cvt x(rolled)->fp16, w_qkv->fp16, w_out->fp16
//   K1: QKV GEMM (fp16 mma + ldmatrix)         -> g_qkv (fp16)
//   K2: attention (fp16 mma, per window-head)  -> g_att (fp16)
//   K3: out GEMM (fp16 mma, roll on write)     -> d_out (fp32)
// tcgen05 unusable: harness ptxas targets sm_103 (no 'a' features).
// ---------------------------------------------------------------------------

#define BATCH   8
#define NSEQ    16384
#define CDIM    256
#define PWIN    64
#define SHIFT   32
#define NHEADS  8
#define HDIM    32
#define MTOT    (BATCH * NSEQ)
#define QKV_N   768
#define NWIN    (MTOT / PWIN)
#define WPB     (NSEQ / PWIN)

__device__ __half g_qkv [(size_t)MTOT * QKV_N];   // fp16 (attention input)
__device__ __half g_att [(size_t)MTOT * CDIM];    // fp16 (K3 input)
__device__ __half g_xh  [(size_t)MTOT * CDIM];    // fp16 rolled x
__device__ __half g_wqkvh[(size_t)QKV_N * CDIM];
__device__ __half g_wouth[(size_t)CDIM * CDIM];

// ---------------------------------------------------------------------------
__device__ __forceinline__ uint32_t smem_u32(const void* p) {
    return (uint32_t)__cvta_generic_to_shared(p);
}
__device__ __forceinline__ void mma_f16(float (&d)[4],
                                        const uint32_t (&a)[4],
                                        const uint32_t (&b)[2]) {
    asm volatile(
        "mma.sync.aligned.m16n8k16.row.col.f32.f16.f16.f32 "
        "{%0,%1,%2,%3}, {%4,%5,%6,%7}, {%8,%9}, {%0,%1,%2,%3};"
        : "+f"(d[0]), "+f"(d[1]), "+f"(d[2]), "+f"(d[3])
        : "r"(a[0]), "r"(a[1]), "r"(a[2]), "r"(a[3]), "r"(b[0]), "r"(b[1]));
}
__device__ __forceinline__ void ldsm_x4(uint32_t (&r)[4], uint32_t addr) {
    asm volatile("ldmatrix.sync.aligned.m8n8.x4.shared.b16 {%0,%1,%2,%3}, [%4];"
        : "=r"(r[0]), "=r"(r[1]), "=r"(r[2]), "=r"(r[3]) : "r"(addr));
}
__device__ __forceinline__ uint32_t h2u(__half2 h) {
    return *reinterpret_cast<uint32_t*>(&h);
}

// ---------------------------------------------------------------------------
// FP16 GEMM: C[m,n] = sum_k A[m,k]*W[n,k] + bias[n]   (A, W fp16)
// BM=BN=128, BK=64, 256 threads = 8 warps, warp tile 64x32, ldmatrix frags.
// Smem stride 72 halves (144B): LDSM phase banks = 4r mod 32, conflict-free.
// ---------------------------------------------------------------------------
#define HBK 64

template<bool ROLL_OUT, typename OutT>
__global__ void __launch_bounds__(256, 2)
gemm_f16_kernel(const __half* __restrict__ A,
                const __half* __restrict__ W,
                const float* __restrict__ bias,
                OutT* __restrict__ Cout,
                int Ncols)
{
    __shared__ __half As[128][72];
    __shared__ __half Bs[128][72];

    const int bm = blockIdx.y * 128;
    const int bn = blockIdx.x * 128;

    const int t    = threadIdx.x;
    const int warp = t >> 5;
    const int lane = t & 31;
    const int g    = lane >> 2;
    const int tg   = lane & 3;

    const int wm = (warp & 1) * 64;
    const int wn = (warp >> 1) * 32;

    // gmem load map: 128 rows x 8 chunks(16B) per matrix, 4 chunks/thread
    int arow[4], ac[4];
#pragma unroll
    for (int i = 0; i < 4; i++) {
        int id = t + i * 256;
        arow[i] = id >> 3;
        ac[i]   = id & 7;
    }
    const __half* Ab = A + (size_t)bm * CDIM;
    const __half* Wb = W + (size_t)bn * CDIM;

    // ldmatrix base addresses
    uint32_t aAddr[4], bAddr[2];
#pragma unroll
    for (int mt = 0; mt < 4; mt++)
        aAddr[mt] = smem_u32(&As[wm + mt * 16 + (lane & 15)][(lane >> 4) * 8]);
#pragma unroll
    for (int ntp = 0; ntp < 2; ntp++)
        bAddr[ntp] = smem_u32(&Bs[wn + ntp * 16 + ((lane >> 4) << 3) + (lane & 7)]
                                 [((lane >> 3) & 1) * 8]);

    float acc[4][4][4];
#pragma unroll
    for (int mt = 0; mt < 4; mt++)
#pragma unroll
        for (int nt = 0; nt < 4; nt++)
#pragma unroll
            for (int r = 0; r < 4; r++) acc[mt][nt][r] = 0.0f;

#pragma unroll 1
    for (int kt = 0; kt < 4; kt++) {
        const int k0 = kt * HBK;

        uint4 av[4], bv[4];
#pragma unroll
        for (int i = 0; i < 4; i++) {
            av[i] = *(const uint4*)(Ab + (size_t)arow[i] * CDIM + k0 + ac[i] * 8);
            bv[i] = *(const uint4*)(Wb + (size_t)arow[i] * CDIM + k0 + ac[i] * 8);
        }

        __syncthreads();
#pragma unroll
        for (int i = 0; i < 4; i++) {
            *(uint4*)&As[arow[i]][ac[i] * 8] = av[i];
            *(uint4*)&Bs[arow[i]][ac[i] * 8] = bv[i];
        }
        __syncthreads();

#pragma unroll
        for (int ks = 0; ks < 4; ks++) {
            const uint32_t koff = ks * 32;   // 16 halves
            uint32_t afr[4][4], bp[2][4];
#pragma unroll
            for (int mt = 0; mt < 4; mt++) ldsm_x4(afr[mt], aAddr[mt] + koff);
#pragma unroll
            for (int ntp = 0; ntp < 2; ntp++) ldsm_x4(bp[ntp], bAddr[ntp] + koff);
#pragma unroll
            for (int mt = 0; mt < 4; mt++)
#pragma unroll
                for (int nt = 0; nt < 4; nt++) {
                    uint32_t bfr[2] = { bp[nt >> 1][(nt & 1) * 2],
                                        bp[nt >> 1][(nt & 1) * 2 + 1] };
                    mma_f16(acc[mt][nt], afr[mt], bfr);
                }
        }
    }

    // ---- epilogue: bias + optional output roll ----
#pragma unroll
    for (int mt = 0; mt < 4; mt++) {
        int m0 = bm + wm + mt * 16 + g;
        int m1 = m0 + 8;
        int bi0 = m0 >> 14, t0 = m0 & 16383;
        int bi1 = m1 >> 14, t1 = m1 & 16383;
        int d0 = ROLL_OUT ? ((t0 + SHIFT) & 16383) : t0;
        int d1 = ROLL_OUT ? ((t1 + SHIFT) & 16383) : t1;
        OutT* row0 = Cout + (size_t)((bi0 << 14) + d0) * Ncols;
        OutT* row1 = Cout + (size_t)((bi1 << 14) + d1) * Ncols;
#pragma unroll
        for (int nt = 0; nt < 4; nt++) {
            int col = bn + wn + nt * 8 + 2 * tg;
            float b0 = bias[col], b1 = bias[col + 1];
            if constexpr (sizeof(OutT) == 4) {
                *(float2*)((float*)row0 + col) =
                    make_float2(acc[mt][nt][0] + b0, acc[mt][nt][1] + b1);
                *(float2*)((float*)row1 + col) =
                    make_float2(acc[mt][nt][2] + b0, acc[mt][nt][3] + b1);
            } else {
                *(uint32_t*)((__half*)row0 + col) =
                    h2u(__floats2half2_rn(acc[mt][nt][0] + b0, acc[mt][nt][1] + b1));
                *(uint32_t*)((__half*)row1 + col) =
                    h2u(__floats2half2_rn(acc[mt][nt][2] + b0, acc[mt][nt][3] + b1));
            }
        }
    }
}

// ---------------------------------------------------------------------------
// cvt pre-passes: fp32 -> fp16
// ---------------------------------------------------------------------------
__global__ void cvt_roll_h_kernel(const float* __restrict__ x, __half* __restrict__ xh)
{
    size_t i4 = (size_t)blockIdx.x * 256 + threadIdx.x;
    size_t fi = i4 * 4;
    int m = (int)(fi >> 8);
    int c = (int)(fi & 255);
    int bi = m >> 14, t = m & 16383;
    int s = (t + SHIFT) & 16383;
    float4 v = *(const float4*)(x + (size_t)((bi << 14) + s) * CDIM + c);
    *(uint2*)(xh + fi) = make_uint2(h2u(__floats2half2_rn(v.x, v.y)),
                                    h2u(__floats2half2_rn(v.z, v.w)));
}

__global__ void cvt_h_kernel(const float* __restrict__ src, __half* __restrict__ dst, int n4)
{
    int i = blockIdx.x * 256 + threadIdx.x;
    if (i < n4) {
        float4 v = *(const float4*)(src + (size_t)i * 4);
        *(uint2*)(dst + (size_t)i * 4) = make_uint2(h2u(__floats2half2_rn(v.x, v.y)),
                                                    h2u(__floats2half2_rn(v.z, v.w)));
    }
}

// ---------------------------------------------------------------------------
// FP16 tensor-core attention. Block = (window, head), 128 threads = 4 warps.
// Warp w owns query rows [16w, 16w+16).
//   S(16x64) = Q K^T   (m16n8k16, 2 k-steps over HD=32)
//   P = exp(S*scale + rel), mask on last window; rowsum via shfl
//   O^T(32x16) = V^T P^T  (4 k-steps over j=64)
// ---------------------------------------------------------------------------
__global__ void __launch_bounds__(128)
attn_f16_kernel(const __half* __restrict__ qkv,
                const float* __restrict__ rel_pos,
                __half* __restrict__ att)
{
    __shared__ __half Qs[64][40];
    __shared__ __half Ks[64][40];
    __shared__ __half VT[32][72];
    __shared__ __half Ps[64][72];
    __shared__ float  Os[64][36];
    __shared__ float  rels[128];
    __shared__ float  sinv[64];

    const int wi = blockIdx.x;
    const int h  = blockIdx.y;
    const int tid  = threadIdx.x;
    const int w    = tid >> 5;
    const int lane = tid & 31;
    const int g    = lane >> 2;
    const int tg   = lane & 3;
    const int mbase = wi * PWIN;
    const bool lastw = ((wi & (WPB - 1)) == (WPB - 1));

    // ---- stage Q, K ([j][d]) and V^T ([d][j]) in fp16 ----
#pragma unroll
    for (int it = 0; it < 2; it++) {
        int idx = tid + it * 128;           // 0..255
        int j = idx >> 2, c8 = (idx & 3) * 8;
        const __half* base = qkv + (size_t)(mbase + j) * QKV_N + h * HDIM + c8;
        uint4 q4 = *(const uint4*)(base);
        uint4 k4 = *(const uint4*)(base + 256);
        uint4 v4 = *(const uint4*)(base + 512);
        *(uint4*)&Qs[j][c8] = q4;
        *(uint4*)&Ks[j][c8] = k4;
        __half vh[8];
        *(uint4*)vh = v4;
#pragma unroll
        for (int d = 0; d < 8; d++) VT[c8 + d][j] = vh[d];
    }
    if (tid < 127) rels[tid] = rel_pos[h * 127 + tid];
    __syncthreads();

    // ---- Q fragments (2 k-steps) ----
    uint32_t qfr[2][4];
    {
        uint32_t qa = smem_u32(&Qs[w * 16 + (lane & 15)][(lane >> 4) * 8]);
        ldsm_x4(qfr[0], qa);
        ldsm_x4(qfr[1], qa + 32);
    }

    // ---- S = Q K^T ----
    float sfr[8][4];
#pragma unroll
    for (int nt = 0; nt < 8; nt++)
#pragma unroll
        for (int r = 0; r < 4; r++) sfr[nt][r] = 0.0f;
    {
        uint32_t kb = smem_u32(&Ks[((lane >> 4) << 3) + (lane & 7)][((lane >> 3) & 1) * 8]);
#pragma unroll
        for (int ks = 0; ks < 2; ks++) {
#pragma unroll
            for (int ntp = 0; ntp < 4; ntp++) {
                uint32_t bb[4];
                ldsm_x4(bb, kb + (uint32_t)(ntp * 16 * 80) + ks * 32);
                uint32_t b0[2] = { bb[0], bb[1] };
                uint32_t b1[2] = { bb[2], bb[3] };
                mma_f16(sfr[ntp * 2],     qfr[ks], b0);
                mma_f16(sfr[ntp * 2 + 1], qfr[ks], b1);
            }
        }
    }

    // ---- softmax (no max-subtraction: logits tiny), mask, P -> smem fp16 ----
    const float scale = 0.17677669529663687f;
    const int i0 = w * 16 + g;
    const int i1 = i0 + 8;
    const int myside = w >> 1;
    float sum0 = 0.0f, sum1 = 0.0f;
#pragma unroll
    for (int nt = 0; nt < 8; nt++) {
        int j0 = nt * 8 + 2 * tg;
        float e00, e01, e10, e11;
        if (lastw && ((nt >> 2) != myside)) {
            e00 = e01 = e10 = e11 = 0.0f;
        } else {
            e00 = __expf(sfr[nt][0] * scale + rels[i0 - j0 + 63]);
            e01 = __expf(sfr[nt][1] * scale + rels[i0 - j0 + 62]);
            e10 = __expf(sfr[nt][2] * scale + rels[i1 - j0 + 63]);
            e11 = __expf(sfr[nt][3] * scale + rels[i1 - j0 + 62]);
        }
        sum0 += e00 + e01;
        sum1 += e10 + e11;
        *(uint32_t*)&Ps[i0][j0] = h2u(__floats2half2_rn(e00, e01));
        *(uint32_t*)&Ps[i1][j0] = h2u(__floats2half2_rn(e10, e11));
    }
    sum0 += __shfl_xor_sync(0xffffffffu, sum0, 1);
    sum0 += __shfl_xor_sync(0xffffffffu, sum0, 2);
    sum1 += __shfl_xor_sync(0xffffffffu, sum1, 1);
    sum1 += __shfl_xor_sync(0xffffffffu, sum1, 2);
    if (tg == 0) { sinv[i0] = 1.0f / sum0; sinv[i1] = 1.0f / sum1; }
    __syncwarp();

    // ---- O^T = V^T x P^T  (warp reads only its own Ps rows) ----
    float ofr[2][2][4];
#pragma unroll
    for (int mt = 0; mt < 2; mt++)
#pragma unroll
        for (int nt = 0; nt < 2; nt++)
#pragma unroll
            for (int r = 0; r < 4; r++) ofr[mt][nt][r] = 0.0f;
    {
        uint32_t va0 = smem_u32(&VT[(lane & 15)][(lane >> 4) * 8]);
        uint32_t va1 = smem_u32(&VT[16 + (lane & 15)][(lane >> 4) * 8]);
        uint32_t pb  = smem_u32(&Ps[w * 16 + ((lane >> 4) << 3) + (lane & 7)]
                                   [((lane >> 3) & 1) * 8]);
#pragma unroll
        for (int ks = 0; ks < 4; ks++) {
            uint32_t a0[4], a1[4], bb[4];
            ldsm_x4(a0, va0 + ks * 32);
            ldsm_x4(a1, va1 + ks * 32);
            ldsm_x4(bb, pb + ks * 32);
            uint32_t b0[2] = { bb[0], bb[1] };
            uint32_t b1[2] = { bb[2], bb[3] };
            mma_f16(ofr[0][0], a0, b0);
            mma_f16(ofr[0][1], a0, b1);
            mma_f16(ofr[1][0], a1, b0);
            mma_f16(ofr[1][1], a1, b1);
        }
    }

    // ---- transpose via fp32 staging, normalize, fp16 writes ----
#pragma unroll
    for (int mt = 0; mt < 2; mt++)
#pragma unroll
        for (int nt = 0; nt < 2; nt++) {
            int d = mt * 16 + g;
            int i = w * 16 + nt * 8 + 2 * tg;
            Os[i][d]         = ofr[mt][nt][0];
            Os[i + 1][d]     = ofr[mt][nt][1];
            Os[i][d + 8]     = ofr[mt][nt][2];
            Os[i + 1][d + 8] = ofr[mt][nt][3];
        }
    __syncthreads();

#pragma unroll
    for (int it = 0; it < 2; it++) {
        int idx = tid + it * 128;
        int i = idx >> 2, d8 = (idx & 3) * 8;
        float inv = sinv[i];
        float4 v0 = *(float4*)&Os[i][d8];
        float4 v1 = *(float4*)&Os[i][d8 + 4];
        uint4 o;
        o.x = h2u(__floats2half2_rn(v0.x * inv, v0.y * inv));
        o.y = h2u(__floats2half2_rn(v0.z * inv, v0.w * inv));
        o.z = h2u(__floats2half2_rn(v1.x * inv, v1.y * inv));
        o.w = h2u(__floats2half2_rn(v1.z * inv, v1.w * inv));
        *(uint4*)(att + (size_t)(mbase + i) * CDIM + h * HDIM + d8) = o;
    }
}

// ---------------------------------------------------------------------------
extern "C" void kernel_launch(void* const* d_in, const int* in_sizes, int n_in,
                              void* d_out, int out_size)
{
    const float* x       = (const float*)d_in[0];
    const float* w_qkv   = (const float*)d_in[1];
    const float* b_qkv   = (const float*)d_in[2];
    const float* rel_pos = (const float*)d_in[3];
    const float* w_out   = (const float*)d_in[4];
    const float* b_out   = (const float*)d_in[5];
    float* out = (float*)d_out;

    __half *qkvp, *attp, *xhp, *wqkvp, *woutp;
    cudaGetSymbolAddress((void**)&qkvp,  g_qkv);
    cudaGetSymbolAddress((void**)&attp,  g_att);
    cudaGetSymbolAddress((void**)&xhp,   g_xh);
    cudaGetSymbolAddress((void**)&wqkvp, g_wqkvh);
    cudaGetSymbolAddress((void**)&woutp, g_wouth);

    // K0: fp16 pre-conversion (roll folded into x copy)
    cvt_roll_h_kernel<<<(MTOT * CDIM / 4) / 256, 256>>>(x, xhp);
    cvt_h_kernel<<<(QKV_N * CDIM / 4 + 255) / 256, 256>>>(w_qkv, wqkvp, QKV_N * CDIM / 4);
    cvt_h_kernel<<<(CDIM * CDIM / 4 + 255) / 256, 256>>>(w_out, woutp, CDIM * CDIM / 4);

    // K1: QKV projection (fp16 out)
    {
        dim3 grid(QKV_N / 128, MTOT / 128);   // (6, 1024)
        gemm_f16_kernel<false, __half><<<grid, 256>>>(xhp, wqkvp, b_qkv, qkvp, QKV_N);
    }
    // K2: windowed attention (fp16 tensor cores)
    {
        dim3 grid(NWIN, NHEADS);
        attn_f16_kernel<<<grid, 128>>>(qkvp, rel_pos, attp);
    }
    // K3: output projection (fp32 out, roll on write)
    {
        dim3 grid(CDIM / 128, MTOT / 128);    // (2, 1024)
        gemm_f16_kernel<true, float><<<grid, 256>>>(attp, woutp, b_out, out, CDIM);
    }
}